// round 17
// baseline (speedup 1.0000x reference)
#include <cuda_runtime.h>
#include <cuda_fp16.h>
#include <math.h>
#include <stdint.h>

// ---------------- problem constants ----------------
#define BQ 16
#define TT 2048
#define ED 1024
#define AD 512
#define DD 1024
#define CD 64
#define KSY 2
#define CK 15
#define KW 31
#define MM (BQ*TT)
#define KK 1088            // ED + CD concatenated K

// ---------------- GEMM tiling: BM128/BN128, BK=64, 1024 tiles ----------------
#define BM 128
#define BN 128
#define BK 64
#define NKIT (KK/BK)       // 17
#define NENCKIT (ED/BK)    // 16
#define NTILES ((MM/BM)*(AD/BN))   // 1024
#define STAGE_BYTES 32768  // A 16K + B 16K
#define SMEM_REQ (3*STAGE_BYTES)   // 96 KB
#define NTHREADS 512       // 16 warps: 2 (m) x 8 (n), warp tile 64x16
#define GRID_P 148

// ---------------- merged prep dispatch ----------------
#define CONV_BLKS 2048                 // 128 t-blocks x 16 batches, 4 t per thread
#define WS_BLKS AD                     // 512
#define DEC_BLKS 1024
#define INIT_BLKS 128
#define PREP_BLKS (CONV_BLKS + WS_BLKS + DEC_BLKS + INIT_BLKS)

// ---------------- scratch ----------------
__device__ __half g_Ahc[(size_t)MM*CD];   // conv features (fp16)
__device__ __half g_Bh[(size_t)AD*KK];
__device__ float  g_decproj[BQ*AD];
__device__ float  g_score[MM];

// ---------------- helpers ----------------
__device__ __forceinline__ uint32_t smem_u32(const void* p){
    uint32_t a;
    asm("{ .reg .u64 t; cvta.to.shared.u64 t, %1; cvt.u32.u64 %0, t; }" : "=r"(a) : "l"(p));
    return a;
}
__device__ __forceinline__ void cp16(uint32_t dst, const void* src){
    asm volatile("cp.async.cg.shared.global [%0], [%1], 16;" :: "r"(dst), "l"(src) : "memory");
}
// 128B rows, 8 x 16B granules, XOR swizzle
__device__ __forceinline__ uint32_t swz128(uint32_t r, uint32_t g){
    return r * 128u + ((g ^ (r & 7u)) << 4);
}
#define MMA16816(d, a, b) \
    asm volatile("mma.sync.aligned.m16n8k16.row.col.f32.f16.f16.f32 " \
        "{%0,%1,%2,%3}, {%4,%5,%6,%7}, {%8,%9}, {%0,%1,%2,%3};" \
        : "+f"((d)[0]), "+f"((d)[1]), "+f"((d)[2]), "+f"((d)[3]) \
        : "r"((a)[0]), "r"((a)[1]), "r"((a)[2]), "r"((a)[3]), \
          "r"((b)[0]), "r"((b)[1]))

// ---------------- merged prep: conv | w_split | dec | init ----------------
__global__ void prep_kernel(const float* __restrict__ state,
                            const float* __restrict__ Wc,
                            const float* __restrict__ We,
                            const float* __restrict__ Wa,
                            const float* __restrict__ h,
                            const float* __restrict__ Wd,
                            const float* __restrict__ be,
                            const float* __restrict__ b_out,
                            float* __restrict__ cctx){
    __shared__ float sW[CD * KSY * KW];
    int bid = blockIdx.x;
    int tid = threadIdx.x;

    if (bid < CONV_BLKS){
        // ---- conv over time -> fp16 [MM, 64]; 4 t per thread ----
        for (int i = tid; i < CD * KSY * KW; i += 256) sW[i] = Wc[i];
        __syncthreads();

        int xb = bid & 127;           // 128 t-blocks of 16
        int b  = bid >> 7;
        int c = tid & 63;
        int tBase = xb * 16 + (tid >> 6) * 4;

        const float* s0 = state + (b * KSY + 0) * TT;
        const float* s1 = state + (b * KSY + 1) * TT;
        const float* w0 = &sW[(c * KSY + 0) * KW];
        const float* w1 = &sW[(c * KSY + 1) * KW];

#pragma unroll
        for (int j = 0; j < 4; ++j){
            int t = tBase + j;
            float acc = 0.f;
#pragma unroll
            for (int hh = 0; hh < KW; ++hh){
                int tt = t + hh - CK;
                bool ok = (tt >= 0) && (tt < TT);
                float v0 = ok ? s0[tt] : 0.f;
                float v1 = ok ? s1[tt] : 0.f;
                acc = fmaf(v0, w0[hh], acc);
                acc = fmaf(v1, w1[hh], acc);
            }
            g_Ahc[(size_t)(b * TT + t) * CD + c] = __float2half_rn(acc);
        }
    } else if (bid < CONV_BLKS + WS_BLKS){
        int n = bid - CONV_BLKS;
        for (int k = tid; k < KK; k += 256){
            float x = (k < ED) ? We[(size_t)n * ED + k] : Wa[n * CD + (k - ED)];
            g_Bh[(size_t)n * KK + k] = __float2half_rn(x);
        }
    } else if (bid < CONV_BLKS + WS_BLKS + DEC_BLKS){
        int bb = bid - CONV_BLKS - WS_BLKS;
        int wgid = (bb * 256 + tid) >> 5;
        int lane = tid & 31;
        int b = wgid >> 9;
        int a = wgid & (AD - 1);
        const float4* hv = (const float4*)(h + b * DD) + lane;
        const float4* wv = (const float4*)(Wd + (size_t)a * DD) + lane;
        float acc = 0.f;
#pragma unroll
        for (int k = 0; k < 8; ++k){
            float4 x = hv[k * 32], w = wv[k * 32];
            acc = fmaf(x.x, w.x, acc); acc = fmaf(x.y, w.y, acc);
            acc = fmaf(x.z, w.z, acc); acc = fmaf(x.w, w.w, acc);
        }
#pragma unroll
        for (int s = 16; s > 0; s >>= 1) acc += __shfl_xor_sync(~0u, acc, s);
        if (lane == 0) g_decproj[wgid] = acc + be[a];
    } else {
        int bb = bid - CONV_BLKS - WS_BLKS - DEC_BLKS;
        int i = bb * 256 + tid;
        if (i < MM) g_score[i] = b_out[0];
        if (i < BQ * ED) cctx[i] = 0.f;
    }
}

// ---------------- persistent fused GEMM, BN=128/BK=64 ----------------
__global__ void __launch_bounds__(NTHREADS, 1)
mma_kernel(const float* __restrict__ enc, const float* __restrict__ Wout){
    extern __shared__ char smraw[];
    uint32_t sbase = smem_u32(smraw);
    int tid = threadIdx.x;
    int lane = tid & 31;
    int wid = tid >> 5;
    int warp_m = wid & 1;       // 0..1  -> 64 rows each
    int warp_n = wid >> 1;      // 0..7  -> 16 cols each

    // producer mapping: thread -> 2 A granules (rows rA0, rA0+64)
    int rA0 = tid >> 3, gA0c = tid & 7;
    uint32_t stsOff0 = swz128((uint32_t)rA0, (uint32_t)gA0c);
    int rA1 = rA0 + 64;
    uint32_t stsOff1 = swz128((uint32_t)rA1, (uint32_t)gA0c);

    // ldmatrix offset components: off = base[f] + ((kb*32 + g0) ^ x)
    uint32_t x16 = (uint32_t)(lane & 7) << 4;
    uint32_t gA0 = (uint32_t)(lane >> 4) << 4;
    uint32_t gB0 = (uint32_t)((lane >> 3) & 1) << 4;
    uint32_t baseA[4], baseB;
#pragma unroll
    for (int fm = 0; fm < 4; ++fm)
        baseA[fm] = (uint32_t)(warp_m * 64 + fm * 16 + (lane & 15)) * 128u;
    baseB = (uint32_t)(warp_n * 16 + (((lane >> 4) & 1) * 8) + (lane & 7)) * 128u + 16384u;

    for (int tile = blockIdx.x; tile < NTILES; tile += gridDim.x){
        int colBase = (tile & 3) * BN;     // 4 col tiles share A rows
        int rowBase = (tile >> 2) * BM;

        __syncthreads();   // previous tile's stage reads all retired

        float acc[4][2][4];
#pragma unroll
        for (int fm = 0; fm < 4; ++fm)
#pragma unroll
            for (int fn = 0; fn < 2; ++fn)
#pragma unroll
                for (int q = 0; q < 4; ++q) acc[fm][fn][q] = 0.f;

        float4 av[4];
        auto ldgA = [&](int k0){
            const float* p0 = enc + (size_t)(rowBase + rA0) * ED + k0 + gA0c * 8;
            const float* p1 = enc + (size_t)(rowBase + rA1) * ED + k0 + gA0c * 8;
            av[0] = *(const float4*)p0; av[1] = *(const float4*)(p0 + 4);
            av[2] = *(const float4*)p1; av[3] = *(const float4*)(p1 + 4);
        };
        auto stsA = [&](uint32_t st){
            const float* xs = (const float*)av;
            uint32_t hq[8];
#pragma unroll
            for (int j = 0; j < 8; ++j){
                __half2 hh = __halves2half2(__float2half_rn(xs[2*j]),
                                            __float2half_rn(xs[2*j+1]));
                hq[j] = *(uint32_t*)&hh;
            }
            asm volatile("st.shared.v4.b32 [%0], {%1,%2,%3,%4};"
                :: "r"(st + stsOff0), "r"(hq[0]), "r"(hq[1]), "r"(hq[2]), "r"(hq[3]) : "memory");
            asm volatile("st.shared.v4.b32 [%0], {%1,%2,%3,%4};"
                :: "r"(st + stsOff1), "r"(hq[4]), "r"(hq[5]), "r"(hq[6]), "r"(hq[7]) : "memory");
        };
        auto cpB = [&](uint32_t st, int k0){
#pragma unroll
            for (int j = 0; j < 2; ++j){
                int i = tid + j * 512;
                int r = i >> 3, g = i & 7;
                cp16(st + 16384u + swz128((uint32_t)r, (uint32_t)g),
                     g_Bh + (size_t)(colBase + r) * KK + k0 + g * 8);
            }
        };
        auto cpConvA = [&](uint32_t st){
            cp16(st + stsOff0, g_Ahc + (size_t)(rowBase + rA0) * CD + gA0c * 8);
            cp16(st + stsOff1, g_Ahc + (size_t)(rowBase + rA1) * CD + gA0c * 8);
        };

        // ---- prologue ----
        ldgA(0);  stsA(sbase);                cpB(sbase, 0);
        asm volatile("cp.async.commit_group;" ::: "memory");
        ldgA(64); stsA(sbase + STAGE_BYTES);  cpB(sbase + STAGE_BYTES, 64);
        asm volatile("cp.async.commit_group;" ::: "memory");
        ldgA(128);

        // ---- mainloop: MMA first, then produce stage it+2 ----
        for (int it = 0; it < NKIT; ++it){
            asm volatile("cp.async.wait_group 1;" ::: "memory");
            __syncthreads();

            uint32_t st = sbase + (uint32_t)(it % 3) * STAGE_BYTES;
#pragma unroll
            for (int kb = 0; kb < 4; ++kb){
                uint32_t gsel = (uint32_t)(kb * 32);
                uint32_t b[2][2];
                asm volatile("ldmatrix.sync.aligned.m8n8.x4.shared.b16 {%0,%1,%2,%3}, [%4];"
                    : "=r"(b[0][0]), "=r"(b[0][1]), "=r"(b[1][0]), "=r"(b[1][1])
                    : "r"(st + baseB + ((gsel + gB0) ^ x16)));
                uint32_t a[4][4];
#pragma unroll
                for (int fm = 0; fm < 4; ++fm)
                    asm volatile("ldmatrix.sync.aligned.m8n8.x4.shared.b16 {%0,%1,%2,%3}, [%4];"
                        : "=r"(a[fm][0]), "=r"(a[fm][1]), "=r"(a[fm][2]), "=r"(a[fm][3])
                        : "r"(st + baseA[fm] + ((gsel + gA0) ^ x16)));
#pragma unroll
                for (int fm = 0; fm < 4; ++fm)
#pragma unroll
                    for (int fn = 0; fn < 2; ++fn)
                        MMA16816(acc[fm][fn], a[fm], b[fn]);
            }

            // ---- produce stage it+2 while tensor pipe drains ----
            int nk = it + 2;
            uint32_t stn = sbase + (uint32_t)(nk % 3) * STAGE_BYTES;
            if (nk < NENCKIT){
                stsA(stn);
                cpB(stn, nk * BK);
                if (nk + 1 < NENCKIT) ldgA((nk + 1) * BK);
            } else if (nk == NENCKIT){
                cpConvA(stn);
                cpB(stn, nk * BK);
            }
            asm volatile("cp.async.commit_group;" ::: "memory");
        }

        // ---- epilogue: +decproj, tanh, dot W_out, reduce + atomic ----
        int b = rowBase >> 11;
        float wo[2][2], dp[2][2];
#pragma unroll
        for (int fn = 0; fn < 2; ++fn){
            int c0 = colBase + warp_n * 16 + fn * 8 + 2 * (lane & 3);
            wo[fn][0] = Wout[c0];               wo[fn][1] = Wout[c0 + 1];
            dp[fn][0] = g_decproj[b * AD + c0]; dp[fn][1] = g_decproj[b * AD + c0 + 1];
        }
        int g = lane >> 2;
#pragma unroll
        for (int fm = 0; fm < 4; ++fm){
            float s0 = 0.f, s1 = 0.f;
#pragma unroll
            for (int fn = 0; fn < 2; ++fn){
                s0 += tanhf(acc[fm][fn][0] + dp[fn][0]) * wo[fn][0];
                s0 += tanhf(acc[fm][fn][1] + dp[fn][1]) * wo[fn][1];
                s1 += tanhf(acc[fm][fn][2] + dp[fn][0]) * wo[fn][0];
                s1 += tanhf(acc[fm][fn][3] + dp[fn][1]) * wo[fn][1];
            }
            s0 += __shfl_xor_sync(~0u, s0, 1); s0 += __shfl_xor_sync(~0u, s0, 2);
            s1 += __shfl_xor_sync(~0u, s1, 1); s1 += __shfl_xor_sync(~0u, s1, 2);
            if ((lane & 3) == 0){
                int row = rowBase + warp_m * 64 + fm * 16 + g;
                atomicAdd(&g_score[row], s0);
                atomicAdd(&g_score[row + 8], s1);
            }
        }
    }
}

// ---------------- softmax over T per batch ----------------
__global__ void softmax_kernel(const unsigned char* __restrict__ mask,
                               float* __restrict__ wout){
    __shared__ float red[256];
    int b = blockIdx.x;
    int tid = threadIdx.x;

    float local[8];
    float mx = -INFINITY;
#pragma unroll
    for (int i = 0; i < 8; ++i){
        int t = i * 256 + tid;
        float v = g_score[b * TT + t];
        if (mask[b * TT + t]) v = -INFINITY;
        local[i] = v;
        mx = fmaxf(mx, v);
    }
    red[tid] = mx; __syncthreads();
    for (int s = 128; s > 0; s >>= 1){
        if (tid < s) red[tid] = fmaxf(red[tid], red[tid + s]);
        __syncthreads();
    }
    mx = red[0]; __syncthreads();

    float sum = 0.f;
#pragma unroll
    for (int i = 0; i < 8; ++i){
        local[i] = expf(2.f * (local[i] - mx));
        sum += local[i];
    }
    red[tid] = sum; __syncthreads();
    for (int s = 128; s > 0; s >>= 1){
        if (tid < s) red[tid] += red[tid + s];
        __syncthreads();
    }
    float inv = 1.f / red[0];
#pragma unroll
    for (int i = 0; i < 8; ++i)
        wout[b * TT + i * 256 + tid] = local[i] * inv;
}

// ---------------- context: float4 per thread, 4 t-phases, 128-row chunks ----
__global__ void context_kernel(const float* __restrict__ enc,
                               const float* __restrict__ w,
                               float* __restrict__ c){
    __shared__ float sw[128];
    __shared__ float4 red[256];
    int tid = threadIdx.x;
    int b = blockIdx.z;
    int t0 = blockIdx.y * 128;
    if (tid < 128) sw[tid] = w[b * TT + t0 + tid];
    __syncthreads();

    int eq = tid & 63;
    int g  = tid >> 6;
    int e  = blockIdx.x * 256 + eq * 4;

    const float4* ep = (const float4*)(enc + ((size_t)(b * TT + t0 + g)) * ED + e);
    float4 acc = make_float4(0.f, 0.f, 0.f, 0.f);
#pragma unroll 8
    for (int j = 0; j < 32; ++j){
        float4 v = ep[(size_t)j * ED];
        float ww = sw[g + j * 4];
        acc.x = fmaf(v.x, ww, acc.x);
        acc.y = fmaf(v.y, ww, acc.y);
        acc.z = fmaf(v.z, ww, acc.z);
        acc.w = fmaf(v.w, ww, acc.w);
    }
    red[tid] = acc;
    __syncthreads();
    if (g == 0){
        float4 a0 = red[eq], a1 = red[eq + 64], a2 = red[eq + 128], a3 = red[eq + 192];
        float* dst = c + b * ED + e;
        atomicAdd(dst + 0, a0.x + a1.x + a2.x + a3.x);
        atomicAdd(dst + 1, a0.y + a1.y + a2.y + a3.y);
        atomicAdd(dst + 2, a0.z + a1.z + a2.z + a3.z);
        atomicAdd(dst + 3, a0.w + a1.w + a2.w + a3.w);
    }
}

// ---------------- launch ----------------
extern "C" void kernel_launch(void* const* d_in, const int* in_sizes, int n_in,
                              void* d_out, int out_size){
    const float*         encoder_out = (const float*)d_in[0];
    const unsigned char* mask        = (const unsigned char*)d_in[1];
    const float*         decoder_h   = (const float*)d_in[2];
    const float*         attn_state  = (const float*)d_in[3];
    const float*         W_enc       = (const float*)d_in[4];
    const float*         b_enc       = (const float*)d_in[5];
    const float*         W_dec       = (const float*)d_in[6];
    const float*         W_attn      = (const float*)d_in[7];
    const float*         W_conv      = (const float*)d_in[8];
    const float*         W_out       = (const float*)d_in[9];
    const float*         b_out       = (const float*)d_in[10];

    float* out_c = (float*)d_out;               // [B, ED]
    float* out_w = (float*)d_out + BQ * ED;     // [B, T]

    cudaFuncSetAttribute(mma_kernel, cudaFuncAttributeMaxDynamicSharedMemorySize, SMEM_REQ);

    prep_kernel<<<PREP_BLKS, 256>>>(attn_state, W_conv, W_enc, W_attn,
                                    decoder_h, W_dec, b_enc, b_out, out_c);
    mma_kernel<<<GRID_P, NTHREADS, SMEM_REQ>>>(encoder_out, W_out);
    softmax_kernel<<<BQ, 256>>>(mask, out_w);
    context_kernel<<<dim3(ED / 256, TT / 128, BQ), 256>>>(encoder_out, out_w, out_c);
}